// round 17
// baseline (speedup 1.0000x reference)
#include <cuda_runtime.h>

// Problem dims (fixed)
#define ND   2048
#define NM   512
#define IN_  256
#define OC   128
#define NTOT 2560
#define NEDG 513
#define NCTA 296
#define NTHR 256
#define NDOC (ND * OC)
#define NMOC (NM * OC)

// smem stage sizes/offsets (floats); 3-stage pipelines, regions overlap per phase
#define A1S 576      // P1/P3 A stage: 16 x 36
#define B1S 4608     // P1 B stage: 128 x 36
#define B1O 1728     // P1 B base (3 x A1S)
#define B3S 4352     // P3/P5 B stage: 32 x 136 (k-major)
#define B3O 1728     // P3 B base (3 x A1S)
#define A5S 1280     // P5 A stage: 32 x 40 (k-major)
#define B5O 3840     // P5 B base (3 x A5S)
#define SX_OFF  16896
#define SAN_OFF 17024
#define SMEMF   17040                    // floats
#define SMEMB   (SMEMF * 4)              // bytes = 68160

// ---------------- device scratch ----------------
__device__ float g_xlin[NTOT * OC];
__device__ float g_anode[NTOT];
__device__ float g_E[ND * NM];
__device__ float g_alpha0[ND];
__device__ float g_e[NDOC];
__device__ float g_p3[16 * NMOC];       // gemm3 split-K partials
__device__ float g_meanc[IN_], g_meanm[IN_], g_vb[IN_];
__device__ float g_convc[OC], g_convm[OC];
__device__ unsigned g_bar[4];           // per-barrier counters (deferred-reset protocol)

__device__ __forceinline__ float lrelu(float x) { return x > 0.f ? x : 0.2f * x; }

// ---------------- cp.async helpers ----------------
__device__ __forceinline__ void cpa16(float* dst_smem, const float* src) {
    unsigned d = (unsigned)__cvta_generic_to_shared(dst_smem);
    asm volatile("cp.async.cg.shared.global [%0], [%1], 16;" :: "r"(d), "l"(src));
}
#define CP_COMMIT() asm volatile("cp.async.commit_group;" ::: "memory")
#define CP_WAIT0()  asm volatile("cp.async.wait_group 0;" ::: "memory")
#define CP_WAIT1()  asm volatile("cp.async.wait_group 1;" ::: "memory")

// ---------------- cheap grid barrier: red.add arrival + ld.cg poll ----------------
// Counter i is monotonic within a launch; resets are deferred to points where no
// CTA can still be polling it (see call sites).
__device__ __forceinline__ void gbar(int i) {
    __syncthreads();
    if (threadIdx.x == 0) {
        __threadfence();
        asm volatile("red.global.add.u32 [%0], 1;" :: "l"(&g_bar[i]) : "memory");
        unsigned v;
        for (;;) {
            asm volatile("ld.global.cg.u32 %0, [%1];" : "=r"(v) : "l"(&g_bar[i]));
            if (v >= NCTA) break;
            __nanosleep(32);
        }
        __threadfence();
    }
    __syncthreads();
}

// ---------------- m16n8k8 tf32 mma, fp32 accumulate ----------------
__device__ __forceinline__ void mma8(float* d, float a0, float a1, float a2, float a3,
                                     float b0, float b1) {
    asm volatile(
        "mma.sync.aligned.m16n8k8.row.col.f32.tf32.tf32.f32 "
        "{%0,%1,%2,%3}, {%4,%5,%6,%7}, {%8,%9}, {%0,%1,%2,%3};"
        : "+f"(d[0]), "+f"(d[1]), "+f"(d[2]), "+f"(d[3])
        : "r"(__float_as_uint(a0)), "r"(__float_as_uint(a1)),
          "r"(__float_as_uint(a2)), "r"(__float_as_uint(a3)),
          "r"(__float_as_uint(b0)), "r"(__float_as_uint(b1)));
}

__global__ __launch_bounds__(NTHR, 2)
void k_fused(const float* __restrict__ cemb, const float* __restrict__ memb,
             const float* __restrict__ Wc,   const float* __restrict__ bc,
             const float* __restrict__ Wg,   const float* __restrict__ att,
             const float* __restrict__ bg,   const float* __restrict__ he,
             float* __restrict__ out) {
    extern __shared__ __align__(16) float smem[];
    float* sX   = smem + SX_OFF;
    float* s_an = smem + SAN_OFF;

    const int cta = blockIdx.x;
    const int t   = threadIdx.x;
    const int w   = t >> 5, lane = t & 31;
    const int g   = lane >> 2, c = lane & 3;
    const int m0w = (w & 1) * 16;     // gemm3 warp m-offset (CTA tile 32)
    const int n0w = (w >> 1) * 32;    // gemm3 warp n-offset
    const int gid = cta * NTHR + t;
    const int tot = NCTA * NTHR;

    // Launch-start: recycle last two barrier counters from the previous replay.
    // Safe: no CTA can reach barrier 2/3 without passing barriers 0,1, which
    // require cta0's arrivals, which are program-ordered after these stores.
    if (cta == 0 && t == 0) {
        *(volatile unsigned*)&g_bar[2] = 0u;
        *(volatile unsigned*)&g_bar[3] = 0u;
        __threadfence();
    }

    // ======== Phase 1: gemm1 (160 CTAs, full-K) + colsums + vb ========
    if (cta < 160) {
        int m0 = cta * 16;
        const float* Ab = (m0 < ND) ? cemb + (size_t)m0 * IN_ : memb + (size_t)(m0 - ND) * IN_;
        if (t < OC) sX[t] = att[t];
        if (t < 16) s_an[t] = 0.f;
        const int nw = w * 16;                        // warp tile m16 x n16
        const int am = t >> 3, ao4 = (t & 7) * 4;
        float acc[2][4] = {};
#pragma unroll
        for (int p = 0; p < 2; p++) {
            int k0 = p * 32;
            if (t < 128) cpa16(smem + p * A1S + am * 36 + ao4, Ab + (size_t)am * IN_ + k0 + ao4);
#pragma unroll
            for (int i = 0; i < 4; i++) {
                int n = i * 32 + am;
                cpa16(smem + B1O + p * B1S + n * 36 + ao4, Wg + (size_t)n * IN_ + k0 + ao4);
            }
            CP_COMMIT();
        }
        for (int sub = 0; sub < 8; sub++) {
            if (sub < 7) CP_WAIT1(); else CP_WAIT0();
            __syncthreads();
            if (sub < 6) {
                int k0n = (sub + 2) * 32, nb = (sub + 2) % 3;
                if (t < 128) cpa16(smem + nb * A1S + am * 36 + ao4,
                                   Ab + (size_t)am * IN_ + k0n + ao4);
#pragma unroll
                for (int i = 0; i < 4; i++) {
                    int n = i * 32 + am;
                    cpa16(smem + B1O + nb * B1S + n * 36 + ao4,
                          Wg + (size_t)n * IN_ + k0n + ao4);
                }
                CP_COMMIT();
            }
            const float* A_ = smem + (sub % 3) * A1S;
            const float* B_ = smem + B1O + (sub % 3) * B1S;
#pragma unroll
            for (int ks = 0; ks < 4; ks++) {
                int kc = ks * 8 + c;
                float a0 = A_[g * 36 + kc],       a0h = A_[g * 36 + kc + 4];
                float a1 = A_[(g + 8) * 36 + kc], a1h = A_[(g + 8) * 36 + kc + 4];
#pragma unroll
                for (int ni = 0; ni < 2; ni++) {
                    float bx = B_[(nw + ni * 8 + g) * 36 + kc];
                    float by = B_[(nw + ni * 8 + g) * 36 + kc + 4];
                    mma8(acc[ni], a0, a1, a0h, a1h, bx, by);
                }
            }
        }
        float an0 = 0.f, an8 = 0.f;
#pragma unroll
        for (int ni = 0; ni < 2; ni++) {
            int col = nw + ni * 8 + 2 * c;
            *(float2*)&g_xlin[(size_t)(m0 + g) * OC + col]     = make_float2(acc[ni][0], acc[ni][1]);
            *(float2*)&g_xlin[(size_t)(m0 + g + 8) * OC + col] = make_float2(acc[ni][2], acc[ni][3]);
            an0 += acc[ni][0] * sX[col] + acc[ni][1] * sX[col + 1];
            an8 += acc[ni][2] * sX[col] + acc[ni][3] * sX[col + 1];
        }
        an0 += __shfl_xor_sync(0xffffffffu, an0, 1);
        an0 += __shfl_xor_sync(0xffffffffu, an0, 2);
        an8 += __shfl_xor_sync(0xffffffffu, an8, 1);
        an8 += __shfl_xor_sync(0xffffffffu, an8, 2);
        if (c == 0) { atomicAdd(&s_an[g], an0); atomicAdd(&s_an[g + 8], an8); }
        __syncthreads();
        if (t < 16) g_anode[m0 + t] = s_an[t];
    } else if (cta < 240) {
        int b = cta - 160;
        const float* base = (b < 64) ? (cemb + (size_t)b * 32 * IN_)
                                     : (memb + (size_t)(b - 64) * 32 * IN_);
        float s = 0.f;
#pragma unroll
        for (int r = 0; r < 32; r++) s += base[r * IN_ + t];
        atomicAdd((b < 64) ? &g_meanc[t] : &g_meanm[t], s);
    } else if (cta == 240) {
        float s = 0.f;
        for (int o = 0; o < OC; o++) s += Wg[o * IN_ + t] * att[OC + o];
        g_vb[t] = s;
    }
    gbar(0);

    // ======== Phase 2: softmax (2048 warp-rows) + conv vectors ========
    {
        float* sf = smem;          // sanm[512] + svb[256]
        if (cta < 256) {
            sf[t]       = g_anode[ND + t];
            sf[256 + t] = g_anode[ND + 256 + t];
            sf[512 + t] = g_vb[t];
        }
        __syncthreads();
        if (cta < 256) {
            int d = cta * 8 + w;
            const float* hb = he + (size_t)d * IN_;
            float ah = 0.f;
#pragma unroll
            for (int j = 0; j < 8; j++) { int i = lane + j * 32; ah += hb[i] * sf[512 + i]; }
#pragma unroll
            for (int s = 16; s > 0; s >>= 1) ah += __shfl_xor_sync(0xffffffffu, ah, s);
            float l[16];
            float mx = -1e30f;
#pragma unroll
            for (int j = 0; j < 16; j++) { l[j] = lrelu(sf[lane + j * 32] + ah); mx = fmaxf(mx, l[j]); }
            float l0 = lrelu(g_anode[d] + ah);
            mx = fmaxf(mx, l0);
#pragma unroll
            for (int s = 16; s > 0; s >>= 1) mx = fmaxf(mx, __shfl_xor_sync(0xffffffffu, mx, s));
            float psum = 0.f;
#pragma unroll
            for (int j = 0; j < 16; j++) { l[j] = __expf(l[j] - mx); psum += l[j]; }
#pragma unroll
            for (int s = 16; s > 0; s >>= 1) psum += __shfl_xor_sync(0xffffffffu, psum, s);
            float e0 = __expf(l0 - mx);
            float inv = 1.f / (psum + e0);
#pragma unroll
            for (int j = 0; j < 16; j++) g_E[(size_t)d * NM + lane + j * 32] = l[j] * inv;
            if (lane == 0) g_alpha0[d] = e0 * inv;
        } else if (cta < 288) {
            int gi = (cta - 256) * 8 + w;   // 0-127 convc, 128-255 convm
            int o = gi & 127;
            const float* mean = (gi < 128) ? g_meanc : g_meanm;
            float s = 0.f;
#pragma unroll
            for (int j = 0; j < 8; j++) { int i = lane + j * 32; s += Wc[o * IN_ + i] * mean[i]; }
#pragma unroll
            for (int sh = 16; sh > 0; sh >>= 1) s += __shfl_xor_sync(0xffffffffu, s, sh);
            if (lane == 0) {
                if (gi < 128) g_convc[o] = s * (1.f / ND) + bc[o];
                else          g_convm[o] = s * (1.f / NM) + bc[o];
            }
        }
    }
    gbar(1);

    // ======== Phase 3: gemm2 FULL-K + fused epilogue-1 (128 CTAs) ========
    // e[m0..m0+16) = (alpha0*xlin_dia + E @ xlin_med) / NEDG ; disease out rows direct.
    if (cta < 128) {
        int m0 = cta * 16;
        const int nw = w * 16;
        const int am = t >> 3, ao4 = (t & 7) * 4;    // A: 16 x 32 (t < 128)
        const int bk = w, bn4 = lane * 4;            // B: k-major 32 x 128
        const float* Bb = g_xlin + (size_t)ND * OC;
        float acc[2][4] = {};
#pragma unroll
        for (int p = 0; p < 2; p++) {
            int k0 = p * 32;
            if (t < 128) cpa16(smem + p * A1S + am * 36 + ao4,
                               g_E + (size_t)(m0 + am) * NM + k0 + ao4);
#pragma unroll
            for (int i = 0; i < 4; i++)
                cpa16(smem + B3O + p * B3S + (i * 8 + bk) * 136 + bn4,
                      Bb + (size_t)(k0 + i * 8 + bk) * OC + bn4);
            CP_COMMIT();
        }
        for (int sub = 0; sub < 16; sub++) {
            if (sub < 15) CP_WAIT1(); else CP_WAIT0();
            __syncthreads();
            if (sub < 14) {
                int k0n = (sub + 2) * 32, nb = (sub + 2) % 3;
                if (t < 128) cpa16(smem + nb * A1S + am * 36 + ao4,
                                   g_E + (size_t)(m0 + am) * NM + k0n + ao4);
#pragma unroll
                for (int i = 0; i < 4; i++)
                    cpa16(smem + B3O + nb * B3S + (i * 8 + bk) * 136 + bn4,
                          Bb + (size_t)(k0n + i * 8 + bk) * OC + bn4);
                CP_COMMIT();
            }
            const float* A_ = smem + (sub % 3) * A1S;
            const float* B_ = smem + B3O + (sub % 3) * B3S;
#pragma unroll
            for (int ks = 0; ks < 4; ks++) {
                int kc = ks * 8 + c;
                float a0 = A_[g * 36 + kc],       a0h = A_[g * 36 + kc + 4];
                float a1 = A_[(g + 8) * 36 + kc], a1h = A_[(g + 8) * 36 + kc + 4];
#pragma unroll
                for (int ni = 0; ni < 2; ni++) {
                    float bx = B_[kc * 136 + nw + ni * 8 + g];
                    float by = B_[(kc + 4) * 136 + nw + ni * 8 + g];
                    mma8(acc[ni], a0, a1, a0h, a1h, bx, by);
                }
            }
        }
        // fused epilogue 1 from fragments
#pragma unroll
        for (int ni = 0; ni < 2; ni++) {
            int col = nw + ni * 8 + 2 * c;
            float b0 = bg[col], b1 = bg[col + 1];
            float cc0 = g_convc[col], cc1 = g_convc[col + 1];
#pragma unroll
            for (int rr = 0; rr < 2; rr++) {
                int r = m0 + g + rr * 8;
                float a0v = g_alpha0[r];
                float x0 = g_xlin[(size_t)r * OC + col];
                float x1 = g_xlin[(size_t)r * OC + col + 1];
                float e0 = (a0v * x0 + acc[ni][rr * 2 + 0]) * (1.f / NEDG);
                float e1 = (a0v * x1 + acc[ni][rr * 2 + 1]) * (1.f / NEDG);
                *(float2*)&g_e[(size_t)r * OC + col] = make_float2(e0, e1);
                *(float2*)&out[(size_t)r * (2 * OC) + col] =
                    make_float2(a0v * e0 + b0, a0v * e1 + b1);
                *(float2*)&out[(size_t)r * (2 * OC) + OC + col] = make_float2(cc0, cc1);
            }
        }
    } else if (cta == 290) {
        // mean resets for next replay (P2 is done reading them)
        g_meanc[t] = 0.f;
        g_meanm[t] = 0.f;
    }
    gbar(2);
    if (cta == 0 && t == 0) *(volatile unsigned*)&g_bar[0] = 0u;  // all CTAs passed bar 2 => done with bar 0

    // ======== Phase 4: gemm3 partials p3[s] = E^T[:,ks] @ e[ks,:] (256 CTAs) ========
    if (cta < 256) {
        int m0 = (cta >> 4) * 32;          // 16 m-tiles of 32
        int ksp = cta & 15;                // ksplit 16, chunk 128 = 4 subchunks
        int kb = ksp * 128;
        const int ak = t >> 3, am4 = (t & 7) * 4;    // A (E^T): 32 k x 32 m
        const int bk = w, bn4 = lane * 4;
        float acc[4][4] = {};
#pragma unroll
        for (int p = 0; p < 2; p++) {
            int k0 = kb + p * 32;
            cpa16(smem + p * A5S + ak * 40 + am4, g_E + (size_t)(k0 + ak) * NM + m0 + am4);
#pragma unroll
            for (int i = 0; i < 4; i++)
                cpa16(smem + B5O + p * B3S + (i * 8 + bk) * 136 + bn4,
                      g_e + (size_t)(k0 + i * 8 + bk) * OC + bn4);
            CP_COMMIT();
        }
        for (int sub = 0; sub < 4; sub++) {
            if (sub < 3) CP_WAIT1(); else CP_WAIT0();
            __syncthreads();
            if (sub < 2) {
                int k0n = kb + (sub + 2) * 32, nb = (sub + 2) % 3;
                cpa16(smem + nb * A5S + ak * 40 + am4,
                      g_E + (size_t)(k0n + ak) * NM + m0 + am4);
#pragma unroll
                for (int i = 0; i < 4; i++)
                    cpa16(smem + B5O + nb * B3S + (i * 8 + bk) * 136 + bn4,
                          g_e + (size_t)(k0n + i * 8 + bk) * OC + bn4);
                CP_COMMIT();
            }
            const float* A_ = smem + (sub % 3) * A5S;
            const float* B_ = smem + B5O + (sub % 3) * B3S;
#pragma unroll
            for (int ks = 0; ks < 4; ks++) {
                int kc = ks * 8 + c;
                float a0 = A_[kc * 40 + m0w + g],       a0h = A_[(kc + 4) * 40 + m0w + g];
                float a1 = A_[kc * 40 + m0w + g + 8],   a1h = A_[(kc + 4) * 40 + m0w + g + 8];
#pragma unroll
                for (int ni = 0; ni < 4; ni++) {
                    float bx = B_[kc * 136 + n0w + ni * 8 + g];
                    float by = B_[(kc + 4) * 136 + n0w + ni * 8 + g];
                    mma8(acc[ni], a0, a1, a0h, a1h, bx, by);
                }
            }
        }
        float* dst = g_p3 + (size_t)ksp * NMOC;
        int r0 = m0 + m0w + g;
#pragma unroll
        for (int ni = 0; ni < 4; ni++) {
            int col = n0w + ni * 8 + 2 * c;
            *(float2*)&dst[(size_t)r0 * OC + col]       = make_float2(acc[ni][0], acc[ni][1]);
            *(float2*)&dst[(size_t)(r0 + 8) * OC + col] = make_float2(acc[ni][2], acc[ni][3]);
        }
    }
    gbar(3);
    if (cta == 0 && t == 0) *(volatile unsigned*)&g_bar[1] = 0u;  // all passed bar 3 => done with bar 1

    // ======== Phase 5: epilogue 2 (sum 16 partials -> medicine rows) ========
    for (int idx = gid; idx < NMOC; idx += tot) {
        int m = idx >> 7, n = idx & 127;
        float s = 0.f;
#pragma unroll
        for (int si = 0; si < 16; si++) s += g_p3[(size_t)si * NMOC + idx];
        out[(size_t)(ND + m) * (2 * OC) + n]      = s * (1.f / ND) + bg[n];
        out[(size_t)(ND + m) * (2 * OC) + OC + n] = g_convm[n];
    }
}

// ---------------- launch: ONE kernel, dynamic smem ----------------
extern "C" void kernel_launch(void* const* d_in, const int* in_sizes, int n_in,
                              void* d_out, int out_size) {
    const float* cemb = (const float*)d_in[2];
    const float* memb = (const float*)d_in[3];
    const float* Wc   = (const float*)d_in[4];
    const float* bc   = (const float*)d_in[5];
    const float* Wg   = (const float*)d_in[6];
    const float* att  = (const float*)d_in[7];
    const float* bg   = (const float*)d_in[8];
    const float* he   = (const float*)d_in[9];
    float* out = (float*)d_out;

    cudaFuncSetAttribute(k_fused, cudaFuncAttributeMaxDynamicSharedMemorySize, SMEMB);
    k_fused<<<NCTA, NTHR, SMEMB>>>(cemb, memb, Wc, bc, Wg, att, bg, he, out);
}